// round 8
// baseline (speedup 1.0000x reference)
#include <cuda_runtime.h>
#include <math.h>

#define C_IN  64
#define C_HID 64
#define C_OUT 40
#define NMAX  50000
#define EMAX  800000

// Scratch (allocation-free rule). 16B aligned for float4 ops on MY buffers.
__device__ __align__(16) float g_h1s[NMAX * C_HID];  // (x @ W1) * dinv[row]
__device__ __align__(16) float g_feat[NMAX * C_HID]; // layer-1 output (post relu)
__device__ __align__(16) float g_h2s[NMAX * C_OUT];  // (feat @ W2) * dinv[row]
__device__ int   g_deg[NMAX];
__device__ float g_dinv[NMAX];
__device__ int   g_start[NMAX + 1];  // CSR row offsets (by dst)
__device__ int   g_cursor[NMAX];     // placement cursors
__device__ int   g_csr[EMAX];        // src ids grouped by dst
__device__ int   g_bsum[256];        // scan block totals

// ---------------------------------------------------------------------------
__global__ void zero_deg_kernel(int N) {
    int i = blockIdx.x * blockDim.x + threadIdx.x;
    if (i < N) g_deg[i] = 0;
}

__global__ void deg_kernel(const int* __restrict__ ei, int E) {
    int e = blockIdx.x * blockDim.x + threadIdx.x;
    if (e < E) atomicAdd(&g_deg[ei[E + e]], 1);
}

// ---------------------------------------------------------------------------
// scan1: per-block (512 elems) exclusive scan of g_deg -> g_start (local),
// block totals -> g_bsum. Warp-shuffle based. (proven in R7)
// ---------------------------------------------------------------------------
__global__ void scan1_kernel(int N) {
    __shared__ int warp_sums[8];
    int t    = threadIdx.x;
    int lane = t & 31;
    int wid  = t >> 5;
    int i0   = blockIdx.x * 512 + 2 * t;

    int a = (i0 < N)     ? g_deg[i0]     : 0;
    int b = (i0 + 1 < N) ? g_deg[i0 + 1] : 0;
    int pair = a + b;

    int v = pair;
#pragma unroll
    for (int o = 1; o < 32; o <<= 1) {
        int u = __shfl_up_sync(0xFFFFFFFFu, v, o);
        if (lane >= o) v += u;
    }
    if (lane == 31) warp_sums[wid] = v;
    __syncthreads();
    if (wid == 0) {
        int w = (lane < 8) ? warp_sums[lane] : 0;
#pragma unroll
        for (int o = 1; o < 32; o <<= 1) {
            int u = __shfl_up_sync(0xFFFFFFFFu, w, o);
            if (lane >= o) w += u;
        }
        if (lane < 8) warp_sums[lane] = w;
    }
    __syncthreads();
    int carry = (wid > 0) ? warp_sums[wid - 1] : 0;
    int incl  = v + carry;
    int excl  = incl - pair;
    if (i0 < N)     g_start[i0]     = excl;
    if (i0 + 1 < N) g_start[i0 + 1] = excl + a;
    if (t == 255)   g_bsum[blockIdx.x] = incl;  // raw block total
}

// ---------------------------------------------------------------------------
// scan3 (fused with old scan2): each block computes its carry by reducing
// g_bsum[0 .. k) in warp 0 (k = blockIdx.x/2 <= ~98), then finalizes
// start/cursor/dinv.
// ---------------------------------------------------------------------------
__global__ void scan3_kernel(int N, int E) {
    __shared__ int s_carry;
    int k = blockIdx.x >> 1;  // index of this block's 512-elem scan1 range
    int t = threadIdx.x;
    if (t < 32) {
        int sum = 0;
        for (int j = t; j < k; j += 32) sum += g_bsum[j];
#pragma unroll
        for (int o = 16; o; o >>= 1) sum += __shfl_xor_sync(0xFFFFFFFFu, sum, o);
        if (t == 0) s_carry = sum;
    }
    __syncthreads();
    int i = blockIdx.x * 256 + t;
    if (i < N) {
        int v = g_start[i] + s_carry;
        g_start[i]  = v;
        g_cursor[i] = v;
        g_dinv[i]   = rsqrtf((float)(g_deg[i] + 1));  // +1 self loop
        if (i == 0) g_start[N] = E;
    }
}

__global__ void fill_csr_kernel(const int* __restrict__ ei, int E) {
    int e = blockIdx.x * blockDim.x + threadIdx.x;
    if (e < E) {
        int s = ei[e];
        int d = ei[E + e];
        int p = atomicAdd(&g_cursor[d], 1);
        g_csr[p] = s;
    }
}

// ---------------------------------------------------------------------------
// Dense GEMM v3: H[r,:] = (X[r,:] @ W) * dinv[r].  K=64 fixed.
// 4 cols x 1 row per thread; full unroll; generous reg budget so ptxas can
// hoist smem loads (the R2-vs-R6 lesson). blockDim = (COUT/4, 16).
// Per warp-k: 1 Xs broadcast wavefront + 2 Ws wavefronts per 4 warp-FMAs.
// ---------------------------------------------------------------------------
template <int CIN, int COUT, bool LAYER1>
__global__ void __launch_bounds__((COUT / 4) * 16)
gemm_kernel(const float* __restrict__ X, const float* __restrict__ W, int N) {
    constexpr int TROWS = 16;
    __shared__ float Xs[TROWS][CIN + 1];
    __shared__ float Ws[CIN * COUT];

    const float* Xin = LAYER1 ? X : g_feat;
    float* H = LAYER1 ? g_h1s : g_h2s;

    constexpr int NTHR = (COUT / 4) * 16;
    const int tid  = threadIdx.y * blockDim.x + threadIdx.x;
    const int row0 = blockIdx.x * TROWS;

    for (int i = tid; i < CIN * COUT / 4; i += NTHR)
        ((float4*)Ws)[i] = ((const float4*)W)[i];

    for (int idx = tid; idx < TROWS * (CIN / 4); idx += NTHR) {
        int r  = idx >> 4;          // 0..15
        int kg = (idx & 15) << 2;   // 0,4,...,60
        float4 v = make_float4(0.f, 0.f, 0.f, 0.f);
        if (row0 + r < N)
            v = *(const float4*)(Xin + (size_t)(row0 + r) * CIN + kg);
        Xs[r][kg + 0] = v.x;
        Xs[r][kg + 1] = v.y;
        Xs[r][kg + 2] = v.z;
        Xs[r][kg + 3] = v.w;
    }
    __syncthreads();

    const int r  = threadIdx.y;
    const int c0 = threadIdx.x * 4;
    float4 acc = make_float4(0.f, 0.f, 0.f, 0.f);
#pragma unroll
    for (int k = 0; k < CIN; k++) {
        float xv = Xs[r][k];
        float4 w = *(const float4*)(Ws + k * COUT + c0);
        acc.x += xv * w.x;
        acc.y += xv * w.y;
        acc.z += xv * w.z;
        acc.w += xv * w.w;
    }

    int row = row0 + r;
    if (row < N) {
        float di = g_dinv[row];
        acc.x *= di; acc.y *= di; acc.z *= di; acc.w *= di;
        *(float4*)(H + (size_t)row * COUT + c0) = acc;
    }
}

// ---------------------------------------------------------------------------
// Layer-1 aggregate: feat[d] = relu(dinv[d]*(h1s[d] + sum_{src->d} h1s[src]) + b1)
// Half-warp (16 lanes x float4 = 64 ch) per node; 2 nodes/warp. (proven R7)
// ---------------------------------------------------------------------------
__global__ void agg1_kernel(const float* __restrict__ b1, int N) {
    int lane = threadIdx.x & 31;
    int warp = (blockIdx.x * blockDim.x + threadIdx.x) >> 5;
    int node = warp * 2 + (lane >> 4);
    if (node >= N) return;
    int sub = lane & 15;

    const float4* hs = (const float4*)g_h1s;
    float4 acc = hs[node * 16 + sub];  // self loop
    int i = g_start[node], end = g_start[node + 1];
#pragma unroll 4
    for (; i < end; i++) {
        float4 a = hs[g_csr[i] * 16 + sub];
        acc.x += a.x; acc.y += a.y; acc.z += a.z; acc.w += a.w;
    }
    float di = g_dinv[node];
    int c = sub * 4;  // scalar bias loads
    float4 o;
    o.x = fmaxf(fmaf(acc.x, di, b1[c + 0]), 0.f);
    o.y = fmaxf(fmaf(acc.y, di, b1[c + 1]), 0.f);
    o.z = fmaxf(fmaf(acc.z, di, b1[c + 2]), 0.f);
    o.w = fmaxf(fmaf(acc.w, di, b1[c + 3]), 0.f);
    ((float4*)g_feat)[node * 16 + sub] = o;
}

// ---------------------------------------------------------------------------
// Layer-2 aggregate + bias + log_softmax. (proven R7)
// ---------------------------------------------------------------------------
__global__ void agg2_kernel(const float* __restrict__ b2,
                            float* __restrict__ out, int N) {
    int lane = threadIdx.x & 31;
    int warp = (blockIdx.x * blockDim.x + threadIdx.x) >> 5;
    int node = warp * 2 + (lane >> 4);
    int sub  = lane & 15;
    bool valid = (node < N) && (sub < 10);
    int nc = (node < N) ? node : 0;

    float4 v = make_float4(-INFINITY, -INFINITY, -INFINITY, -INFINITY);
    if (valid) {
        const float4* hs = (const float4*)g_h2s;
        float4 acc = hs[nc * 10 + sub];  // self loop
        int i = g_start[nc], end = g_start[nc + 1];
#pragma unroll 4
        for (; i < end; i++) {
            float4 a = hs[g_csr[i] * 10 + sub];
            acc.x += a.x; acc.y += a.y; acc.z += a.z; acc.w += a.w;
        }
        float di = g_dinv[nc];
        int c = sub * 4;
        v = make_float4(fmaf(acc.x, di, b2[c + 0]),
                        fmaf(acc.y, di, b2[c + 1]),
                        fmaf(acc.z, di, b2[c + 2]),
                        fmaf(acc.w, di, b2[c + 3]));
    }

    float m = fmaxf(fmaxf(v.x, v.y), fmaxf(v.z, v.w));
#pragma unroll
    for (int o = 8; o; o >>= 1) m = fmaxf(m, __shfl_xor_sync(0xFFFFFFFFu, m, o));

    float s = valid ? (expf(v.x - m) + expf(v.y - m) + expf(v.z - m) + expf(v.w - m))
                    : 0.f;
#pragma unroll
    for (int o = 8; o; o >>= 1) s += __shfl_xor_sync(0xFFFFFFFFu, s, o);

    float lg = m + logf(s);
    if (valid) {
        float4 o4 = make_float4(v.x - lg, v.y - lg, v.z - lg, v.w - lg);
        ((float4*)out)[nc * 10 + sub] = o4;
    }
}

// ---------------------------------------------------------------------------
extern "C" void kernel_launch(void* const* d_in, const int* in_sizes, int n_in,
                              void* d_out, int out_size) {
    const float* x  = (const float*)d_in[0];
    const int*   ei = (const int*)d_in[1];
    const float* W1 = (const float*)d_in[2];
    const float* b1 = (const float*)d_in[3];
    const float* W2 = (const float*)d_in[4];
    const float* b2 = (const float*)d_in[5];
    float* out = (float*)d_out;

    int N  = in_sizes[0] / C_IN;
    int E  = in_sizes[1] / 2;
    int nb = (N + 511) / 512;

    // Degree + normalization + CSR build
    zero_deg_kernel<<<(N + 255) / 256, 256>>>(N);
    deg_kernel<<<(E + 255) / 256, 256>>>(ei, E);
    scan1_kernel<<<nb, 256>>>(N);
    scan3_kernel<<<(N + 255) / 256, 256>>>(N, E);
    fill_csr_kernel<<<(E + 255) / 256, 256>>>(ei, E);

    // Layer 1
    gemm_kernel<C_IN, C_HID, true><<<(N + 15) / 16, dim3(C_HID / 4, 16)>>>(x, W1, N);
    agg1_kernel<<<(N + 15) / 16, 256>>>(b1, N);

    // Layer 2
    gemm_kernel<C_HID, C_OUT, false><<<(N + 15) / 16, dim3(C_OUT / 4, 16)>>>(nullptr, W2, N);
    agg2_kernel<<<(N + 15) / 16, 256>>>(b2, out, N);
}

// round 9
// speedup vs baseline: 1.2602x; 1.2602x over previous
#include <cuda_runtime.h>
#include <math.h>

#define C_IN  64
#define C_HID 64
#define C_OUT 40
#define NMAX  50000
#define EMAX  800000

// Scratch (allocation-free rule). 16B aligned for float4 ops on MY buffers.
__device__ __align__(16) float g_h1[NMAX * C_HID];   // x @ W1 (UNSCALED)
__device__ __align__(16) float g_feat[NMAX * C_HID]; // layer-1 output (post relu)
__device__ __align__(16) float g_h2s[NMAX * C_OUT];  // (feat @ W2) * dinv[row]
__device__ int   g_deg[NMAX];
__device__ float g_dinv[NMAX];
__device__ int   g_start[NMAX + 1];  // CSR row offsets (by dst)
__device__ int   g_cursor[NMAX];     // placement cursors
__device__ int   g_csr[EMAX];        // src ids grouped by dst
__device__ int   g_bsum[256];        // scan block totals

// ---------------------------------------------------------------------------
__global__ void zero_deg_kernel(int N) {
    int i = blockIdx.x * blockDim.x + threadIdx.x;
    if (i < N) g_deg[i] = 0;
}

// ---------------------------------------------------------------------------
// Shared GEMM tile body (R7-proven shape): thread-per-output-column,
// 64-row tiles, W + X staged in smem. Optionally scales store by dinv[row].
// ---------------------------------------------------------------------------
template <int CIN, int COUT, bool SCALE>
__device__ __forceinline__ void gemm_tile(const float* __restrict__ Xin,
                                          const float* __restrict__ W,
                                          float* __restrict__ H,
                                          int N, int row0) {
    constexpr int ROWS = 64;
    __shared__ float Ws[CIN * COUT];
    __shared__ float Xs[ROWS * CIN];

    int tid  = threadIdx.y * blockDim.x + threadIdx.x;
    int nthr = blockDim.x * blockDim.y;

    for (int i = tid; i < CIN * COUT; i += nthr) Ws[i] = W[i];

    int nrows = min(ROWS, N - row0);
    for (int i = tid; i < nrows * CIN; i += nthr) Xs[i] = Xin[(size_t)row0 * CIN + i];
    __syncthreads();

    int c = threadIdx.x;
    for (int r = threadIdx.y; r < nrows; r += blockDim.y) {
        float acc = 0.f;
#pragma unroll
        for (int k = 0; k < CIN; k++) acc += Xs[r * CIN + k] * Ws[k * COUT + c];
        float o = acc;
        if (SCALE) o *= g_dinv[row0 + r];
        H[(size_t)(row0 + r) * COUT + c] = o;
    }
}

// ---------------------------------------------------------------------------
// Fused A: first half of gemm1 (unscaled)  ||  degree histogram of dst nodes.
// Blocks [0, GA): gemm; blocks [GA, GA+DB): grid-stride atomic degree count.
// ---------------------------------------------------------------------------
__global__ void __launch_bounds__(256)
fusedA_kernel(const float* __restrict__ x, const float* __restrict__ W1,
              const int* __restrict__ ei, int E, int N, int GA, int DB) {
    if ((int)blockIdx.x < GA) {
        gemm_tile<C_IN, C_HID, false>(x, W1, g_h1, N, blockIdx.x * 64);
    } else {
        int tid = threadIdx.y * blockDim.x + threadIdx.x;
        for (int e = ((int)blockIdx.x - GA) * 256 + tid; e < E; e += DB * 256)
            atomicAdd(&g_deg[ei[E + e]], 1);
    }
}

// ---------------------------------------------------------------------------
// Fused B: second half of gemm1 (unscaled)  ||  CSR fill.
// Blocks [0, GB): gemm rows offset by GA tiles; blocks [GB, GB+FB): fill.
// ---------------------------------------------------------------------------
__global__ void __launch_bounds__(256)
fusedB_kernel(const float* __restrict__ x, const float* __restrict__ W1,
              const int* __restrict__ ei, int E, int N, int GA, int GB, int FB) {
    if ((int)blockIdx.x < GB) {
        gemm_tile<C_IN, C_HID, false>(x, W1, g_h1, N, (GA + blockIdx.x) * 64);
    } else {
        int tid = threadIdx.y * blockDim.x + threadIdx.x;
        for (int e = ((int)blockIdx.x - GB) * 256 + tid; e < E; e += FB * 256) {
            int s = ei[e];
            int d = ei[E + e];
            int p = atomicAdd(&g_cursor[d], 1);
            g_csr[p] = s;
        }
    }
}

// ---------------------------------------------------------------------------
// scan1: per-block (512 elems) exclusive scan of g_deg -> g_start (local),
// block totals -> g_bsum. Warp-shuffle based. (proven R7)
// ---------------------------------------------------------------------------
__global__ void scan1_kernel(int N) {
    __shared__ int warp_sums[8];
    int t    = threadIdx.x;
    int lane = t & 31;
    int wid  = t >> 5;
    int i0   = blockIdx.x * 512 + 2 * t;

    int a = (i0 < N)     ? g_deg[i0]     : 0;
    int b = (i0 + 1 < N) ? g_deg[i0 + 1] : 0;
    int pair = a + b;

    int v = pair;
#pragma unroll
    for (int o = 1; o < 32; o <<= 1) {
        int u = __shfl_up_sync(0xFFFFFFFFu, v, o);
        if (lane >= o) v += u;
    }
    if (lane == 31) warp_sums[wid] = v;
    __syncthreads();
    if (wid == 0) {
        int w = (lane < 8) ? warp_sums[lane] : 0;
#pragma unroll
        for (int o = 1; o < 32; o <<= 1) {
            int u = __shfl_up_sync(0xFFFFFFFFu, w, o);
            if (lane >= o) w += u;
        }
        if (lane < 8) warp_sums[lane] = w;
    }
    __syncthreads();
    int carry = (wid > 0) ? warp_sums[wid - 1] : 0;
    int incl  = v + carry;
    int excl  = incl - pair;
    if (i0 < N)     g_start[i0]     = excl;
    if (i0 + 1 < N) g_start[i0 + 1] = excl + a;
    if (t == 255)   g_bsum[blockIdx.x] = incl;  // raw block total
}

// ---------------------------------------------------------------------------
// scan3: each block reduces g_bsum[0..k) for its carry (k <= ~98), then
// finalizes start/cursor/dinv. (proven R8)
// ---------------------------------------------------------------------------
__global__ void scan3_kernel(int N, int E) {
    __shared__ int s_carry;
    int k = blockIdx.x >> 1;  // this block's 512-elem scan1 range index
    int t = threadIdx.x;
    if (t < 32) {
        int sum = 0;
        for (int j = t; j < k; j += 32) sum += g_bsum[j];
#pragma unroll
        for (int o = 16; o; o >>= 1) sum += __shfl_xor_sync(0xFFFFFFFFu, sum, o);
        if (t == 0) s_carry = sum;
    }
    __syncthreads();
    int i = blockIdx.x * 256 + t;
    if (i < N) {
        int v = g_start[i] + s_carry;
        g_start[i]  = v;
        g_cursor[i] = v;
        g_dinv[i]   = rsqrtf((float)(g_deg[i] + 1));  // +1 self loop
        if (i == 0) g_start[N] = E;
    }
}

// ---------------------------------------------------------------------------
// Layer-1 aggregate with per-src scaling (h1 is unscaled now):
//   feat[d] = relu(dinv[d] * (dinv[d]*h1[d] + sum_{s->d} dinv[s]*h1[s]) + b1)
// Half-warp (16 lanes x float4 = 64 ch) per node; 2 nodes/warp.
// ---------------------------------------------------------------------------
__global__ void agg1_kernel(const float* __restrict__ b1, int N) {
    int lane = threadIdx.x & 31;
    int warp = (blockIdx.x * blockDim.x + threadIdx.x) >> 5;
    int node = warp * 2 + (lane >> 4);
    if (node >= N) return;
    int sub = lane & 15;

    const float4* hs = (const float4*)g_h1;
    float dn = g_dinv[node];

    float4 self = hs[node * 16 + sub];
    float4 acc;
    acc.x = self.x * dn; acc.y = self.y * dn;
    acc.z = self.z * dn; acc.w = self.w * dn;

    int i = g_start[node], end = g_start[node + 1];
#pragma unroll 4
    for (; i < end; i++) {
        int s = g_csr[i];
        float ds = g_dinv[s];
        float4 a = hs[s * 16 + sub];
        acc.x = fmaf(a.x, ds, acc.x);
        acc.y = fmaf(a.y, ds, acc.y);
        acc.z = fmaf(a.z, ds, acc.z);
        acc.w = fmaf(a.w, ds, acc.w);
    }
    int c = sub * 4;  // scalar bias loads
    float4 o;
    o.x = fmaxf(fmaf(acc.x, dn, b1[c + 0]), 0.f);
    o.y = fmaxf(fmaf(acc.y, dn, b1[c + 1]), 0.f);
    o.z = fmaxf(fmaf(acc.z, dn, b1[c + 2]), 0.f);
    o.w = fmaxf(fmaf(acc.w, dn, b1[c + 3]), 0.f);
    ((float4*)g_feat)[node * 16 + sub] = o;
}

// ---------------------------------------------------------------------------
// Layer 2 GEMM: g_h2s[r,:] = (g_feat[r,:] @ W2) * dinv[r]. (R7-proven shape)
// ---------------------------------------------------------------------------
__global__ void gemm2_kernel(const float* __restrict__ W, int N) {
    gemm_tile<C_HID, C_OUT, true>(g_feat, W, g_h2s, N, blockIdx.x * 64);
}

// ---------------------------------------------------------------------------
// Layer-2 aggregate + bias + log_softmax. (proven R7; h2s is pre-scaled)
// ---------------------------------------------------------------------------
__global__ void agg2_kernel(const float* __restrict__ b2,
                            float* __restrict__ out, int N) {
    int lane = threadIdx.x & 31;
    int warp = (blockIdx.x * blockDim.x + threadIdx.x) >> 5;
    int node = warp * 2 + (lane >> 4);
    int sub  = lane & 15;
    bool valid = (node < N) && (sub < 10);
    int nc = (node < N) ? node : 0;

    float4 v = make_float4(-INFINITY, -INFINITY, -INFINITY, -INFINITY);
    if (valid) {
        const float4* hs = (const float4*)g_h2s;
        float4 acc = hs[nc * 10 + sub];  // self loop
        int i = g_start[nc], end = g_start[nc + 1];
#pragma unroll 4
        for (; i < end; i++) {
            float4 a = hs[g_csr[i] * 10 + sub];
            acc.x += a.x; acc.y += a.y; acc.z += a.z; acc.w += a.w;
        }
        float di = g_dinv[nc];
        int c = sub * 4;
        v = make_float4(fmaf(acc.x, di, b2[c + 0]),
                        fmaf(acc.y, di, b2[c + 1]),
                        fmaf(acc.z, di, b2[c + 2]),
                        fmaf(acc.w, di, b2[c + 3]));
    }

    float m = fmaxf(fmaxf(v.x, v.y), fmaxf(v.z, v.w));
#pragma unroll
    for (int o = 8; o; o >>= 1) m = fmaxf(m, __shfl_xor_sync(0xFFFFFFFFu, m, o));

    float s = valid ? (expf(v.x - m) + expf(v.y - m) + expf(v.z - m) + expf(v.w - m))
                    : 0.f;
#pragma unroll
    for (int o = 8; o; o >>= 1) s += __shfl_xor_sync(0xFFFFFFFFu, s, o);

    float lg = m + logf(s);
    if (valid) {
        float4 o4 = make_float4(v.x - lg, v.y - lg, v.z - lg, v.w - lg);
        ((float4*)out)[nc * 10 + sub] = o4;
    }
}

// ---------------------------------------------------------------------------
extern "C" void kernel_launch(void* const* d_in, const int* in_sizes, int n_in,
                              void* d_out, int out_size) {
    const float* x  = (const float*)d_in[0];
    const int*   ei = (const int*)d_in[1];
    const float* W1 = (const float*)d_in[2];
    const float* b1 = (const float*)d_in[3];
    const float* W2 = (const float*)d_in[4];
    const float* b2 = (const float*)d_in[5];
    float* out = (float*)d_out;

    int N  = in_sizes[0] / C_IN;
    int E  = in_sizes[1] / 2;
    int nb = (N + 511) / 512;

    int G  = (N + 63) / 64;   // total gemm1 tiles
    int GA = (G + 1) / 2;     // first-half tiles (with deg)
    int GB = G - GA;          // second-half tiles (with fill)
    int DB = 1024;            // deg blocks
    int FB = 1024;            // fill blocks

    zero_deg_kernel<<<(N + 255) / 256, 256>>>(N);
    fusedA_kernel<<<GA + DB, dim3(64, 4)>>>(x, W1, ei, E, N, GA, DB);
    scan1_kernel<<<nb, 256>>>(N);
    scan3_kernel<<<(N + 255) / 256, 256>>>(N, E);
    fusedB_kernel<<<GB + FB, dim3(64, 4)>>>(x, W1, ei, E, N, GA, GB, FB);
    agg1_kernel<<<(N + 15) / 16, 256>>>(b1, N);
    gemm2_kernel<<<G, dim3(C_OUT, 6)>>>(W2, N);
    agg2_kernel<<<(N + 15) / 16, 256>>>(b2, out, N);
}